// round 2
// baseline (speedup 1.0000x reference)
#include <cuda_runtime.h>

// Problem constants (fixed shapes)
#define BB   4
#define SS   4096
#define DD   2048
#define DH   1024
#define MTOK (BB * SS)   // 16384 tokens

// Scratch (static device globals; no allocations allowed)
__device__ float g_o1[(size_t)MTOK * DH];   // conv1 output   (64 MB)
__device__ float g_y [(size_t)MTOK * DD];   // pre-norm y     (128 MB)

// ---------------------------------------------------------------------------
// Fused 2-tap temporal conv as GEMM:
//   C[g, n] = sum_k W[n,k,0]*A[g-1, k] + W[n,k,1]*A[g, k] + bias[n] (+ resid)
// where A[g-1] at a batch boundary comes from cache[b, :].
// Tile: BM=128 tokens x BN=128 outs x BK=16. A-tile holds 129 rows
// (tokens g0-1 .. g0+127); prev(row i) = As[i], cur(row i) = As[i+1].
// S % BM == 0 so only the first A-tile row can cross a batch boundary.
// ---------------------------------------------------------------------------
template <int K, bool HAS_RESID>
__global__ __launch_bounds__(256, 2)
void conv_gemm(const float* __restrict__ A,      // [MTOK, K]
               const float* __restrict__ cache,  // [BB, K]
               const float* __restrict__ W,      // [N, K, 2]
               const float* __restrict__ bias,   // [N]
               const float* __restrict__ resid,  // [MTOK, N] (if HAS_RESID)
               float* __restrict__ C,            // [MTOK, N]
               int N)
{
    constexpr int BM = 128, BN = 128, BK = 16;
    constexpr int LDA = BM + 4;  // 132: 16B-aligned rows, bank offset 4/row
    __shared__ float As [BK][LDA];   // As[k][r], r = 0..128
    __shared__ float Bs0[BK][LDA];
    __shared__ float Bs1[BK][LDA];

    const int tid = threadIdx.x;
    const int g0  = blockIdx.y * BM;
    const int n0  = blockIdx.x * BN;
    const int b   = g0 / SS;
    const bool atBoundary = (g0 % SS) == 0;

    const int ty = tid >> 4;          // 0..15 -> row group
    const int tx = tid & 15;          // 0..15 -> col group

    float acc[2][4][2][4];
    #pragma unroll
    for (int r = 0; r < 2; r++)
        #pragma unroll
        for (int i = 0; i < 4; i++)
            #pragma unroll
            for (int c = 0; c < 2; c++)
                #pragma unroll
                for (int j = 0; j < 4; j++)
                    acc[r][i][c][j] = 0.f;

    for (int k0 = 0; k0 < K; k0 += BK) {
        // ---- load A tile: 129 rows x 16 cols, float4 per slot ----
        #pragma unroll
        for (int idx = tid; idx < 129 * 4; idx += 256) {
            int r  = idx >> 2;
            int c4 = (idx & 3) * 4;
            const float* src;
            if (r == 0 && atBoundary)
                src = cache + (size_t)b * K + k0 + c4;
            else
                src = A + (size_t)(g0 - 1 + r) * K + k0 + c4;
            float4 v = *(const float4*)src;
            As[c4 + 0][r] = v.x;
            As[c4 + 1][r] = v.y;
            As[c4 + 2][r] = v.z;
            As[c4 + 3][r] = v.w;
        }
        // ---- load W tile: 128 outs x 16 k, tap pair as float2 ----
        #pragma unroll
        for (int idx = tid; idx < BN * BK / 8; idx += 256) {
            // 8 consecutive (n,k) pairs per thread? keep simple: 1 float2 each
        }
        for (int idx = tid; idx < BN * BK; idx += 256) {
            int n = idx >> 4;
            int k = idx & 15;
            float2 v = *(const float2*)(W + ((size_t)(n0 + n) * K + (k0 + k)) * 2);
            Bs0[k][n] = v.x;
            Bs1[k][n] = v.y;
        }
        __syncthreads();

        #pragma unroll
        for (int k = 0; k < BK; k++) {
            float a[2][5];
            #pragma unroll
            for (int r = 0; r < 2; r++) {
                int rb = r * 64 + ty * 4;
                float4 t = *(const float4*)&As[k][rb];
                a[r][0] = t.x; a[r][1] = t.y; a[r][2] = t.z; a[r][3] = t.w;
                a[r][4] = As[k][rb + 4];
            }
            float4 b0v[2], b1v[2];
            #pragma unroll
            for (int c = 0; c < 2; c++) {
                int cb = c * 64 + tx * 4;
                b0v[c] = *(const float4*)&Bs0[k][cb];
                b1v[c] = *(const float4*)&Bs1[k][cb];
            }
            #pragma unroll
            for (int r = 0; r < 2; r++) {
                #pragma unroll
                for (int c = 0; c < 2; c++) {
                    float b0a[4] = {b0v[c].x, b0v[c].y, b0v[c].z, b0v[c].w};
                    float b1a[4] = {b1v[c].x, b1v[c].y, b1v[c].z, b1v[c].w};
                    #pragma unroll
                    for (int i = 0; i < 4; i++)
                        #pragma unroll
                        for (int j = 0; j < 4; j++)
                            acc[r][i][c][j] += a[r][i] * b0a[j] + a[r][i + 1] * b1a[j];
                }
            }
        }
        __syncthreads();
    }

    // ---- epilogue: + bias (+ residual) ----
    #pragma unroll
    for (int r = 0; r < 2; r++) {
        #pragma unroll
        for (int i = 0; i < 4; i++) {
            int g = g0 + r * 64 + ty * 4 + i;
            #pragma unroll
            for (int c = 0; c < 2; c++) {
                #pragma unroll
                for (int j = 0; j < 4; j++) {
                    int n = n0 + c * 64 + tx * 4 + j;
                    float v = acc[r][i][c][j] + bias[n];
                    if (HAS_RESID) v += resid[(size_t)g * N + n];
                    C[(size_t)g * N + n] = v;
                }
            }
        }
    }
}

// ---------------------------------------------------------------------------
// RMSNorm over D=2048, one CTA per token row.
// ---------------------------------------------------------------------------
__global__ __launch_bounds__(256)
void rmsnorm_kernel(const float* __restrict__ y,
                    const float* __restrict__ ln_w,
                    float* __restrict__ out)
{
    const int g = blockIdx.x;
    const float4* row = (const float4*)(y + (size_t)g * DD);
    float4 v[2];
    float s = 0.f;
    #pragma unroll
    for (int r = 0; r < 2; r++) {
        v[r] = row[threadIdx.x + r * 256];
        s += v[r].x * v[r].x + v[r].y * v[r].y + v[r].z * v[r].z + v[r].w * v[r].w;
    }
    // block reduce
    __shared__ float red[8];
    #pragma unroll
    for (int o = 16; o; o >>= 1) s += __shfl_down_sync(0xffffffffu, s, o);
    if ((threadIdx.x & 31) == 0) red[threadIdx.x >> 5] = s;
    __syncthreads();
    if (threadIdx.x < 32) {
        float t = (threadIdx.x < 8) ? red[threadIdx.x] : 0.f;
        #pragma unroll
        for (int o = 4; o; o >>= 1) t += __shfl_down_sync(0xffffffffu, t, o);
        if (threadIdx.x == 0) red[0] = t;
    }
    __syncthreads();
    const float inv = rsqrtf(red[0] * (1.0f / DD) + 1e-6f);
    float4* orow = (float4*)(out + (size_t)g * DD);
    const float4* wrow = (const float4*)ln_w;
    #pragma unroll
    for (int r = 0; r < 2; r++) {
        float4 w = wrow[threadIdx.x + r * 256];
        float4 o;
        o.x = v[r].x * inv * w.x;
        o.y = v[r].y * inv * w.y;
        o.z = v[r].z * inv * w.z;
        o.w = v[r].w * inv * w.w;
        orow[threadIdx.x + r * 256] = o;
    }
}

// ---------------------------------------------------------------------------
// New caches: lf1 = x[:, S-1, :] (BxD), lf2 = o1[:, S-1, :] (BxDH)
// ---------------------------------------------------------------------------
__global__ void write_caches(const float* __restrict__ x,
                             const float* __restrict__ o1,
                             float* __restrict__ out_lf1,
                             float* __restrict__ out_lf2)
{
    int i = blockIdx.x * blockDim.x + threadIdx.x;
    if (i < BB * DD) {
        int b = i / DD, d = i % DD;
        out_lf1[i] = x[((size_t)b * SS + SS - 1) * DD + d];
    }
    if (i < BB * DH) {
        int b = i / DH, e = i % DH;
        out_lf2[i] = o1[((size_t)b * SS + SS - 1) * DH + e];
    }
}

extern "C" void kernel_launch(void* const* d_in, const int* in_sizes, int n_in,
                              void* d_out, int out_size)
{
    const float* x    = (const float*)d_in[0];  // [B*S, D]
    const float* lf1c = (const float*)d_in[1];  // [B, D]
    const float* lf2c = (const float*)d_in[2];  // [B, DH]
    const float* w1   = (const float*)d_in[3];  // [DH, D, 2]
    const float* b1   = (const float*)d_in[4];  // [DH]
    const float* w2   = (const float*)d_in[5];  // [D, DH, 2]
    const float* b2   = (const float*)d_in[6];  // [D]
    const float* lnw  = (const float*)d_in[7];  // [D]
    float* out = (float*)d_out;

    float *o1, *y;
    cudaGetSymbolAddress((void**)&o1, g_o1);
    cudaGetSymbolAddress((void**)&y,  g_y);

    // conv1: [MTOK, D] -> [MTOK, DH]
    {
        dim3 grid(DH / 128, MTOK / 128);
        conv_gemm<DD, false><<<grid, 256>>>(x, lf1c, w1, b1, nullptr, o1, DH);
    }
    // conv2 + bias + residual: [MTOK, DH] -> [MTOK, D], y = o2 + x
    {
        dim3 grid(DD / 128, MTOK / 128);
        conv_gemm<DH, true><<<grid, 256>>>(o1, lf2c, w2, b2, x, y, DD);
    }
    // RMSNorm -> lf_output
    rmsnorm_kernel<<<MTOK, 256>>>(y, lnw, out);

    // caches appended after lf_output if the output buffer carries them
    const long long main_sz = (long long)MTOK * DD;
    if ((long long)out_size >= main_sz + BB * DD + BB * DH) {
        write_caches<<<(BB * DD + 255) / 256, 256>>>(
            x, o1, out + main_sz, out + main_sz + BB * DD);
    }
}

// round 4
// speedup vs baseline: 3.0041x; 3.0041x over previous
#include <cuda_runtime.h>
#include <cuda_bf16.h>
#include <cstdint>

#define BB 4
#define SS 4096
#define DD 2048
#define DHALF 1024
#define MTOK (BB * SS)          // 16384
#define STRIDE_T (SS + 1)       // 4097
#define MVAL (BB * STRIDE_T)    // 16388
#define MPAD 16640              // 130 * 128

// ---------------- scratch ----------------
__device__ __nv_bfloat16 g_xe_h[(size_t)MPAD * DD];
__device__ __nv_bfloat16 g_xe_l[(size_t)MPAD * DD];
__device__ __nv_bfloat16 g_w1_h[(size_t)2048 * 2048];
__device__ __nv_bfloat16 g_w1_l[(size_t)2048 * 2048];
__device__ __nv_bfloat16 g_w2_h[(size_t)4096 * 1024];
__device__ __nv_bfloat16 g_w2_l[(size_t)4096 * 1024];
__device__ __nv_bfloat16 g_o1_h[(size_t)MPAD * DHALF];
__device__ __nv_bfloat16 g_o1_l[(size_t)MPAD * DHALF];
__device__ float         g_Y  [(size_t)MPAD * 4096];
__device__ float         g_sink[BB * DD];

// ---------------- helpers ----------------
__device__ __forceinline__ void cp16(uint32_t dst, const void* src) {
    asm volatile("cp.async.cg.shared.global [%0], [%1], 16;" :: "r"(dst), "l"(src));
}
__device__ __forceinline__ void ldm_x4(uint32_t a, uint32_t* r) {
    asm volatile("ldmatrix.sync.aligned.m8n8.x4.shared.b16 {%0,%1,%2,%3}, [%4];"
                 : "=r"(r[0]), "=r"(r[1]), "=r"(r[2]), "=r"(r[3]) : "r"(a));
}
__device__ __forceinline__ void mma16816(float* c, const uint32_t* a, uint32_t b0, uint32_t b1) {
    asm volatile(
        "mma.sync.aligned.m16n8k16.row.col.f32.bf16.bf16.f32 "
        "{%0,%1,%2,%3}, {%4,%5,%6,%7}, {%8,%9}, {%0,%1,%2,%3};"
        : "+f"(c[0]), "+f"(c[1]), "+f"(c[2]), "+f"(c[3])
        : "r"(a[0]), "r"(a[1]), "r"(a[2]), "r"(a[3]), "r"(b0), "r"(b1));
}

// ---------------- bf16x3 GEMM via mma.sync: Y[M,NTOT] = A[M,K] @ B[N,K]^T --
// CTA 128x128, 8 warps (2 x 4), warp tile 64x32. BK=64, 3-stage cp.async.
// SW128 swizzle: 16B chunk c (0..7) at row r stored at chunk c^(r&7).
#define BKC      64
#define TILE_B   (128 * BKC * 2)    // 16 KB per bf16 tile
#define STAGE_B  (4 * TILE_B)       // Ah Al Bh Bl
#define NSTAGE   3
#define SMEM_DYN (NSTAGE * STAGE_B) // 192 KB

template <int KTOT, int NTOT>
__global__ __launch_bounds__(256, 1)
void gemm_mma(const __nv_bfloat16* __restrict__ Ah,
              const __nv_bfloat16* __restrict__ Al,
              const __nv_bfloat16* __restrict__ Bh,
              const __nv_bfloat16* __restrict__ Bl,
              float* __restrict__ Y)
{
    constexpr int KCH = KTOT / BKC;
    extern __shared__ char smem_raw[];
    const uint32_t sbase = (uint32_t)__cvta_generic_to_shared(smem_raw);
    const int tid  = threadIdx.x;
    const int wid  = tid >> 5, lane = tid & 31;
    const int wm   = wid >> 2, wn = wid & 3;       // 2 x 4 warp grid
    const int m0   = blockIdx.y * 128, n0 = blockIdx.x * 128;

    float acc[4][4][4];   // [mi 16][ni 8][reg]
    #pragma unroll
    for (int i = 0; i < 4; i++)
        #pragma unroll
        for (int j = 0; j < 4; j++)
            #pragma unroll
            for (int q = 0; q < 4; q++) acc[i][j][q] = 0.f;

    auto load_tile = [&](uint32_t dst, const __nv_bfloat16* src, int kc) {
        #pragma unroll
        for (int u = 0; u < 4; u++) {
            int idx = u * 256 + tid;
            int r = idx >> 3, c = idx & 7;
            cp16(dst + (uint32_t)(r * 128 + ((c ^ (r & 7)) * 16)),
                 src + (size_t)r * KTOT + kc + c * 8);
        }
    };
    auto load_chunk = [&](int ch, int s) {
        const int kc = ch * BKC;
        const uint32_t st = sbase + s * STAGE_B;
        load_tile(st + 0 * TILE_B, Ah + (size_t)m0 * KTOT, kc);
        load_tile(st + 1 * TILE_B, Al + (size_t)m0 * KTOT, kc);
        load_tile(st + 2 * TILE_B, Bh + (size_t)n0 * KTOT, kc);
        load_tile(st + 3 * TILE_B, Bl + (size_t)n0 * KTOT, kc);
        asm volatile("cp.async.commit_group;" ::: "memory");
    };

    #pragma unroll
    for (int ch = 0; ch < NSTAGE - 1; ch++) load_chunk(ch, ch);

    // per-warp ldmatrix row indices (constant across chunks)
    const int ra = wm * 64 + (lane & 15);          // + mi*16
    const int rb = wn * 32 + (lane & 15);          // + nf*16
    const int chi = lane >> 4;                     // 16B-chunk half-select

    for (int ch = 0; ch < KCH; ch++) {
        const int s = ch % NSTAGE;
        asm volatile("cp.async.wait_group %0;" :: "n"(NSTAGE - 2) : "memory");
        __syncthreads();
        if (ch + NSTAGE - 1 < KCH) load_chunk(ch + NSTAGE - 1, (ch + NSTAGE - 1) % NSTAGE);
        else asm volatile("cp.async.commit_group;" ::: "memory");

        const uint32_t st = sbase + s * STAGE_B;
        #pragma unroll
        for (int s16 = 0; s16 < BKC / 16; s16++) {
            const int c = s16 * 2 + chi;
            uint32_t ah[4][4], al[4][4];
            #pragma unroll
            for (int mi = 0; mi < 4; mi++) {
                const int r = ra + mi * 16;
                const uint32_t off = (uint32_t)(r * 128 + ((c ^ (r & 7)) * 16));
                ldm_x4(st + 0 * TILE_B + off, ah[mi]);
                ldm_x4(st + 1 * TILE_B + off, al[mi]);
            }
            uint32_t bh[2][4], bl[2][4];
            #pragma unroll
            for (int nf = 0; nf < 2; nf++) {
                const int r = rb + nf * 16;
                const uint32_t off = (uint32_t)(r * 128 + ((c ^ (r & 7)) * 16));
                ldm_x4(st + 2 * TILE_B + off, bh[nf]);
                ldm_x4(st + 3 * TILE_B + off, bl[nf]);
            }
            #pragma unroll
            for (int mi = 0; mi < 4; mi++) {
                #pragma unroll
                for (int ni = 0; ni < 4; ni++) {
                    const int nf = ni >> 1, p = ni & 1;
                    mma16816(acc[mi][ni], ah[mi], bh[nf][p], bh[nf][p + 2]);
                    mma16816(acc[mi][ni], al[mi], bh[nf][p], bh[nf][p + 2]);
                    mma16816(acc[mi][ni], ah[mi], bl[nf][p], bl[nf][p + 2]);
                }
            }
        }
    }

    // epilogue: direct fp32 stores
    const int er = lane >> 2, ec = (lane & 3) * 2;
    #pragma unroll
    for (int mi = 0; mi < 4; mi++) {
        const int gr = m0 + wm * 64 + mi * 16 + er;
        #pragma unroll
        for (int ni = 0; ni < 4; ni++) {
            const int gc = n0 + wn * 32 + ni * 8 + ec;
            *(float2*)(Y + (size_t)gr * NTOT + gc)       = make_float2(acc[mi][ni][0], acc[mi][ni][1]);
            *(float2*)(Y + (size_t)(gr + 8) * NTOT + gc) = make_float2(acc[mi][ni][2], acc[mi][ni][3]);
        }
    }
}

// ---------------- pack / combine ----------------
__device__ __forceinline__ void split2(float a, float b, uint32_t& h, uint32_t& l) {
    __nv_bfloat16 ha = __float2bfloat16(a), hb = __float2bfloat16(b);
    __nv_bfloat16 la = __float2bfloat16(a - __bfloat162float(ha));
    __nv_bfloat16 lb = __float2bfloat16(b - __bfloat162float(hb));
    __nv_bfloat162 th = __nv_bfloat162(ha, hb), tl = __nv_bfloat162(la, lb);
    h = *(uint32_t*)&th; l = *(uint32_t*)&tl;
}
__device__ __forceinline__ void split8_store(const float* f, __nv_bfloat16* ph_, __nv_bfloat16* pl_) {
    uint4 uh, ul;
    split2(f[0], f[1], uh.x, ul.x);
    split2(f[2], f[3], uh.y, ul.y);
    split2(f[4], f[5], uh.z, ul.z);
    split2(f[6], f[7], uh.w, ul.w);
    *(uint4*)ph_ = uh; *(uint4*)pl_ = ul;
}

__global__ __launch_bounds__(256)
void pack_x(const float* __restrict__ x, const float* __restrict__ lf1c,
            __nv_bfloat16* __restrict__ xh, __nv_bfloat16* __restrict__ xl)
{
    const int r = blockIdx.x, e = threadIdx.x * 8;
    float f[8] = {0, 0, 0, 0, 0, 0, 0, 0};
    if (r < MVAL) {
        const int b = r / STRIDE_T, i = r % STRIDE_T;
        const float* src = (i == 0) ? (lf1c + (size_t)b * DD + e)
                                    : (x + ((size_t)b * SS + (i - 1)) * DD + e);
        float4 v0 = ((const float4*)src)[0], v1 = ((const float4*)src)[1];
        f[0]=v0.x; f[1]=v0.y; f[2]=v0.z; f[3]=v0.w; f[4]=v1.x; f[5]=v1.y; f[6]=v1.z; f[7]=v1.w;
    }
    split8_store(f, xh + (size_t)r * DD + e, xl + (size_t)r * DD + e);
}

__global__ __launch_bounds__(256)
void pack_w1(const float* __restrict__ w1, __nv_bfloat16* __restrict__ bh, __nv_bfloat16* __restrict__ bl)
{
    const int n = blockIdx.x, k = threadIdx.x * 8;
    const int tap = n >> 10, ch = n & 1023;
    const float2* src = (const float2*)w1 + (size_t)ch * DD + k;
    float f[8];
    #pragma unroll
    for (int j = 0; j < 8; j++) { float2 v = src[j]; f[j] = tap ? v.y : v.x; }
    split8_store(f, bh + (size_t)n * DD + k, bl + (size_t)n * DD + k);
}

__global__ __launch_bounds__(128)
void pack_w2(const float* __restrict__ w2, __nv_bfloat16* __restrict__ bh, __nv_bfloat16* __restrict__ bl)
{
    const int n = blockIdx.x, k = threadIdx.x * 8;
    const int tap = n >> 11, ch = n & 2047;
    const float2* src = (const float2*)w2 + (size_t)ch * DHALF + k;
    float f[8];
    #pragma unroll
    for (int j = 0; j < 8; j++) { float2 v = src[j]; f[j] = tap ? v.y : v.x; }
    split8_store(f, bh + (size_t)n * DHALF + k, bl + (size_t)n * DHALF + k);
}

// o1[b,t,e] = Y1[row, e] + Y1[row+1, 1024+e] + b1[e];  row = b*4097+t
__global__ __launch_bounds__(128)
void combine1(const float* __restrict__ Y1, const float* __restrict__ b1,
              __nv_bfloat16* __restrict__ oh, __nv_bfloat16* __restrict__ ol,
              float* __restrict__ lf2_out)
{
    const int g = blockIdx.x, b = g / SS, t = g % SS;
    const size_t row = (size_t)b * STRIDE_T + t;
    const int e = threadIdx.x * 8;
    const float4* p0 = (const float4*)(Y1 + row * 2048 + e);
    const float4* p1 = (const float4*)(Y1 + (row + 1) * 2048 + 1024 + e);
    const float4* pb = (const float4*)(b1 + e);
    float f[8];
    #pragma unroll
    for (int q = 0; q < 2; q++) {
        float4 a = p0[q], c = p1[q], d = pb[q];
        f[q*4+0] = a.x + c.x + d.x; f[q*4+1] = a.y + c.y + d.y;
        f[q*4+2] = a.z + c.z + d.z; f[q*4+3] = a.w + c.w + d.w;
    }
    split8_store(f, oh + (row + 1) * DHALF + e, ol + (row + 1) * DHALF + e);
    if (t == SS - 1) {
        float* dst = lf2_out + (size_t)b * DHALF + e;
        #pragma unroll
        for (int j = 0; j < 8; j++) dst[j] = f[j];
    }
}

__global__ __launch_bounds__(128)
void o1e_extras(const float* __restrict__ lf2c,
                __nv_bfloat16* __restrict__ oh, __nv_bfloat16* __restrict__ ol)
{
    const int idx = blockIdx.x, e = threadIdx.x * 8;
    size_t row;
    float f[8] = {0, 0, 0, 0, 0, 0, 0, 0};
    if (idx < BB) {
        row = (size_t)idx * STRIDE_T;
        const float4* src = (const float4*)(lf2c + (size_t)idx * DHALF + e);
        float4 v0 = src[0], v1 = src[1];
        f[0]=v0.x; f[1]=v0.y; f[2]=v0.z; f[3]=v0.w; f[4]=v1.x; f[5]=v1.y; f[6]=v1.z; f[7]=v1.w;
    } else {
        row = (size_t)MVAL + (idx - BB);
    }
    split8_store(f, oh + row * DHALF + e, ol + row * DHALF + e);
}

__global__ __launch_bounds__(256)
void combine2_rms(const float* __restrict__ Y2, const float* __restrict__ b2,
                  const float* __restrict__ x, const float* __restrict__ lnw,
                  float* __restrict__ out)
{
    const int g = blockIdx.x, b = g / SS, t = g % SS;
    const size_t row = (size_t)b * STRIDE_T + t;
    const float4* p0 = (const float4*)(Y2 + row * 4096);
    const float4* p1 = (const float4*)(Y2 + (row + 1) * 4096 + 2048);
    const float4* px = (const float4*)(x + (size_t)g * DD);
    const float4* pb = (const float4*)b2;
    float4 v[2];
    float s = 0.f;
    #pragma unroll
    for (int r = 0; r < 2; r++) {
        const int i = threadIdx.x + r * 256;
        float4 a = p0[i], c = p1[i], d = pb[i], xr = px[i];
        v[r].x = a.x + c.x + d.x + xr.x; v[r].y = a.y + c.y + d.y + xr.y;
        v[r].z = a.z + c.z + d.z + xr.z; v[r].w = a.w + c.w + d.w + xr.w;
        s += v[r].x*v[r].x + v[r].y*v[r].y + v[r].z*v[r].z + v[r].w*v[r].w;
    }
    __shared__ float red[8];
    #pragma unroll
    for (int o = 16; o; o >>= 1) s += __shfl_down_sync(0xffffffffu, s, o);
    if ((threadIdx.x & 31) == 0) red[threadIdx.x >> 5] = s;
    __syncthreads();
    if (threadIdx.x < 32) {
        float tt = (threadIdx.x < 8) ? red[threadIdx.x] : 0.f;
        #pragma unroll
        for (int o = 4; o; o >>= 1) tt += __shfl_down_sync(0xffffffffu, tt, o);
        if (threadIdx.x == 0) red[0] = tt;
    }
    __syncthreads();
    const float inv = rsqrtf(red[0] * (1.0f / DD) + 1e-6f);
    float4* orow = (float4*)(out + (size_t)g * DD);
    const float4* pw = (const float4*)lnw;
    #pragma unroll
    for (int r = 0; r < 2; r++) {
        const int i = threadIdx.x + r * 256;
        float4 w = pw[i];
        orow[i] = make_float4(v[r].x * inv * w.x, v[r].y * inv * w.y,
                              v[r].z * inv * w.z, v[r].w * inv * w.w);
    }
}

__global__ void write_lf1(const float* __restrict__ x, float* __restrict__ out_lf1)
{
    int i = blockIdx.x * blockDim.x + threadIdx.x;
    if (i < BB * DD) {
        int b = i / DD, d = i % DD;
        out_lf1[i] = x[((size_t)b * SS + SS - 1) * DD + d];
    }
}

extern "C" void kernel_launch(void* const* d_in, const int* in_sizes, int n_in,
                              void* d_out, int out_size)
{
    const float* x    = (const float*)d_in[0];
    const float* lf1c = (const float*)d_in[1];
    const float* lf2c = (const float*)d_in[2];
    const float* w1   = (const float*)d_in[3];
    const float* b1   = (const float*)d_in[4];
    const float* w2   = (const float*)d_in[5];
    const float* b2   = (const float*)d_in[6];
    const float* lnw  = (const float*)d_in[7];
    float* out = (float*)d_out;

    __nv_bfloat16 *xh, *xl, *w1h, *w1l, *w2h, *w2l, *oh, *ol;
    float *Y, *sink;
    cudaGetSymbolAddress((void**)&xh,  g_xe_h);
    cudaGetSymbolAddress((void**)&xl,  g_xe_l);
    cudaGetSymbolAddress((void**)&w1h, g_w1_h);
    cudaGetSymbolAddress((void**)&w1l, g_w1_l);
    cudaGetSymbolAddress((void**)&w2h, g_w2_h);
    cudaGetSymbolAddress((void**)&w2l, g_w2_l);
    cudaGetSymbolAddress((void**)&oh,  g_o1_h);
    cudaGetSymbolAddress((void**)&ol,  g_o1_l);
    cudaGetSymbolAddress((void**)&Y,   g_Y);
    cudaGetSymbolAddress((void**)&sink, g_sink);

    cudaFuncSetAttribute(gemm_mma<2048, 2048>,
                         cudaFuncAttributeMaxDynamicSharedMemorySize, SMEM_DYN);
    cudaFuncSetAttribute(gemm_mma<1024, 4096>,
                         cudaFuncAttributeMaxDynamicSharedMemorySize, SMEM_DYN);

    const long long main_sz = (long long)MTOK * DD;
    const bool carry = (long long)out_size >= main_sz + BB * DD + BB * DHALF;
    float* lf1_out = carry ? out + main_sz : sink;
    float* lf2_out = carry ? out + main_sz + BB * DD : sink;

    pack_x <<<MPAD, 256>>>(x, lf1c, xh, xl);
    pack_w1<<<2048, 256>>>(w1, w1h, w1l);
    pack_w2<<<4096, 128>>>(w2, w2h, w2l);
    o1e_extras<<<BB + (MPAD - MVAL), 128>>>(lf2c, oh, ol);

    {   // GEMM1: [MPAD,2048] @ [2048,2048]^T -> Y (stride 2048)
        dim3 grid(2048 / 128, MPAD / 128);
        gemm_mma<2048, 2048><<<grid, 256, SMEM_DYN>>>(xh, xl, w1h, w1l, Y);
    }
    combine1<<<MTOK, 128>>>(Y, b1, oh, ol, lf2_out);
    {   // GEMM2: [MPAD,1024] @ [4096,1024]^T -> Y (stride 4096)
        dim3 grid(4096 / 128, MPAD / 128);
        gemm_mma<1024, 4096><<<grid, 256, SMEM_DYN>>>(oh, ol, w2h, w2l, Y);
    }
    combine2_rms<<<MTOK, 256>>>(Y, b2, x, lnw, out);
    if (carry) write_lf1<<<(BB * DD + 255) / 256, 256>>>(x, lf1_out);
}

// round 6
// speedup vs baseline: 8.0485x; 2.6792x over previous
#include <cuda_runtime.h>
#include <cuda_fp16.h>
#include <cstdint>

#define BB 4
#define SS 4096
#define DD 2048
#define DHALF 1024
#define MTOK (BB * SS)          // 16384
#define STRIDE_T (SS + 1)       // 4097
#define MVAL (BB * STRIDE_T)    // 16388
#define MPAD 16640              // 130 * 128

// ---------------- scratch ----------------
__device__ __half g_xe [(size_t)MPAD * DD];
__device__ __half g_w1c[(size_t)2048 * 2048];
__device__ __half g_w2c[(size_t)4096 * 1024];
__device__ __half g_o1 [(size_t)MPAD * DHALF];
__device__ float  g_Y  [(size_t)MPAD * 4096];
__device__ float  g_sink[BB * DD];

// ---------------- helpers ----------------
__device__ __forceinline__ void cp16(uint32_t dst, const void* src) {
    asm volatile("cp.async.cg.shared.global [%0], [%1], 16;" :: "r"(dst), "l"(src));
}
__device__ __forceinline__ void ldm_x4(uint32_t a, uint32_t* r) {
    asm volatile("ldmatrix.sync.aligned.m8n8.x4.shared.b16 {%0,%1,%2,%3}, [%4];"
                 : "=r"(r[0]), "=r"(r[1]), "=r"(r[2]), "=r"(r[3]) : "r"(a));
}
__device__ __forceinline__ void mma16816(float* c, const uint32_t* a, uint32_t b0, uint32_t b1) {
    asm volatile(
        "mma.sync.aligned.m16n8k16.row.col.f32.f16.f16.f32 "
        "{%0,%1,%2,%3}, {%4,%5,%6,%7}, {%8,%9}, {%0,%1,%2,%3};"
        : "+f"(c[0]), "+f"(c[1]), "+f"(c[2]), "+f"(c[3])
        : "r"(a[0]), "r"(a[1]), "r"(a[2]), "r"(a[3]), "r"(b0), "r"(b1));
}

// ---------------- fp16 GEMM via mma.sync: Y[M,NTOT] = A[M,K] @ B[N,K]^T ----
// CTA 128x128, 8 warps (2 x 4), warp tile 64x32. BK=64, 3-stage cp.async,
// 2 CTAs/SM. Swizzle: 16B chunk c (0..7) at row r stored at chunk c^(r&7).
#define BKC      64
#define TILE_B   (128 * BKC * 2)    // 16 KB per fp16 tile
#define STAGE_B  (2 * TILE_B)       // A, B
#define NSTAGE   3
#define SMEM_DYN (NSTAGE * STAGE_B) // 96 KB

template <int KTOT, int NTOT>
__global__ __launch_bounds__(256, 2)
void gemm_mma(const __half* __restrict__ A,
              const __half* __restrict__ B,
              float* __restrict__ Y)
{
    constexpr int KCH = KTOT / BKC;
    extern __shared__ char smem_raw[];
    const uint32_t sbase = (uint32_t)__cvta_generic_to_shared(smem_raw);
    const int tid  = threadIdx.x;
    const int wid  = tid >> 5, lane = tid & 31;
    const int wm   = wid >> 2, wn = wid & 3;       // 2 x 4 warp grid
    const int m0   = blockIdx.y * 128, n0 = blockIdx.x * 128;

    float acc[4][4][4];   // [mi 16][ni 8][reg]
    #pragma unroll
    for (int i = 0; i < 4; i++)
        #pragma unroll
        for (int j = 0; j < 4; j++)
            #pragma unroll
            for (int q = 0; q < 4; q++) acc[i][j][q] = 0.f;

    auto load_tile = [&](uint32_t dst, const __half* src, int kc) {
        #pragma unroll
        for (int u = 0; u < 4; u++) {
            int idx = u * 256 + tid;
            int r = idx >> 3, c = idx & 7;
            cp16(dst + (uint32_t)(r * 128 + ((c ^ (r & 7)) * 16)),
                 src + (size_t)r * KTOT + kc + c * 8);
        }
    };
    auto load_chunk = [&](int ch, int s) {
        const int kc = ch * BKC;
        const uint32_t st = sbase + s * STAGE_B;
        load_tile(st + 0 * TILE_B, A + (size_t)m0 * KTOT, kc);
        load_tile(st + 1 * TILE_B, B + (size_t)n0 * KTOT, kc);
        asm volatile("cp.async.commit_group;" ::: "memory");
    };

    #pragma unroll
    for (int ch = 0; ch < NSTAGE - 1; ch++) load_chunk(ch, ch);

    const int ra = wm * 64 + (lane & 15);          // + mi*16
    const int rb = wn * 32 + (lane & 15);          // + nf*16
    const int chi = lane >> 4;                     // 16B-chunk half-select

    for (int ch = 0; ch < KCH; ch++) {
        const int s = ch % NSTAGE;
        asm volatile("cp.async.wait_group %0;" :: "n"(NSTAGE - 2) : "memory");
        __syncthreads();
        if (ch + NSTAGE - 1 < KCH) load_chunk(ch + NSTAGE - 1, (ch + NSTAGE - 1) % NSTAGE);
        else asm volatile("cp.async.commit_group;" ::: "memory");

        const uint32_t st = sbase + s * STAGE_B;
        #pragma unroll
        for (int s16 = 0; s16 < BKC / 16; s16++) {
            const int c = s16 * 2 + chi;
            uint32_t ah[4][4];
            #pragma unroll
            for (int mi = 0; mi < 4; mi++) {
                const int r = ra + mi * 16;
                ldm_x4(st + 0 * TILE_B + (uint32_t)(r * 128 + ((c ^ (r & 7)) * 16)), ah[mi]);
            }
            uint32_t bh[2][4];
            #pragma unroll
            for (int nf = 0; nf < 2; nf++) {
                const int r = rb + nf * 16;
                ldm_x4(st + 1 * TILE_B + (uint32_t)(r * 128 + ((c ^ (r & 7)) * 16)), bh[nf]);
            }
            #pragma unroll
            for (int mi = 0; mi < 4; mi++) {
                #pragma unroll
                for (int ni = 0; ni < 4; ni++) {
                    const int nf = ni >> 1, p = ni & 1;
                    mma16816(acc[mi][ni], ah[mi], bh[nf][p], bh[nf][p + 2]);
                }
            }
        }
    }

    const int er = lane >> 2, ec = (lane & 3) * 2;
    #pragma unroll
    for (int mi = 0; mi < 4; mi++) {
        const int gr = m0 + wm * 64 + mi * 16 + er;
        #pragma unroll
        for (int ni = 0; ni < 4; ni++) {
            const int gc = n0 + wn * 32 + ni * 8 + ec;
            *(float2*)(Y + (size_t)gr * NTOT + gc)       = make_float2(acc[mi][ni][0], acc[mi][ni][1]);
            *(float2*)(Y + (size_t)(gr + 8) * NTOT + gc) = make_float2(acc[mi][ni][2], acc[mi][ni][3]);
        }
    }
}

// ---------------- pack / combine ----------------
__device__ __forceinline__ uint32_t pack2h(float a, float b) {
    __half2 h = __floats2half2_rn(a, b);
    return *(uint32_t*)&h;
}
__device__ __forceinline__ void conv8_store(const float* f, __half* p) {
    uint4 u;
    u.x = pack2h(f[0], f[1]);
    u.y = pack2h(f[2], f[3]);
    u.z = pack2h(f[4], f[5]);
    u.w = pack2h(f[6], f[7]);
    *(uint4*)p = u;
}

__global__ __launch_bounds__(256)
void pack_x(const float* __restrict__ x, const float* __restrict__ lf1c,
            __half* __restrict__ xh)
{
    const int r = blockIdx.x, e = threadIdx.x * 8;
    float f[8] = {0, 0, 0, 0, 0, 0, 0, 0};
    if (r < MVAL) {
        const int b = r / STRIDE_T, i = r % STRIDE_T;
        const float* src = (i == 0) ? (lf1c + (size_t)b * DD + e)
                                    : (x + ((size_t)b * SS + (i - 1)) * DD + e);
        float4 v0 = ((const float4*)src)[0], v1 = ((const float4*)src)[1];
        f[0]=v0.x; f[1]=v0.y; f[2]=v0.z; f[3]=v0.w; f[4]=v1.x; f[5]=v1.y; f[6]=v1.z; f[7]=v1.w;
    }
    conv8_store(f, xh + (size_t)r * DD + e);
}

__global__ __launch_bounds__(256)
void pack_w1(const float* __restrict__ w1, __half* __restrict__ bh)
{
    const int n = blockIdx.x, k = threadIdx.x * 8;
    const int tap = n >> 10, ch = n & 1023;
    const float2* src = (const float2*)w1 + (size_t)ch * DD + k;
    float f[8];
    #pragma unroll
    for (int j = 0; j < 8; j++) { float2 v = src[j]; f[j] = tap ? v.y : v.x; }
    conv8_store(f, bh + (size_t)n * DD + k);
}

__global__ __launch_bounds__(128)
void pack_w2(const float* __restrict__ w2, __half* __restrict__ bh)
{
    const int n = blockIdx.x, k = threadIdx.x * 8;
    const int tap = n >> 11, ch = n & 2047;
    const float2* src = (const float2*)w2 + (size_t)ch * DHALF + k;
    float f[8];
    #pragma unroll
    for (int j = 0; j < 8; j++) { float2 v = src[j]; f[j] = tap ? v.y : v.x; }
    conv8_store(f, bh + (size_t)n * DHALF + k);
}

// o1[b,t,e] = Y1[row, e] + Y1[row+1, 1024+e] + b1[e];  row = b*4097+t
__global__ __launch_bounds__(128)
void combine1(const float* __restrict__ Y1, const float* __restrict__ b1,
              __half* __restrict__ oh, float* __restrict__ lf2_out)
{
    const int g = blockIdx.x, b = g / SS, t = g % SS;
    const size_t row = (size_t)b * STRIDE_T + t;
    const int e = threadIdx.x * 8;
    const float4* p0 = (const float4*)(Y1 + row * 2048 + e);
    const float4* p1 = (const float4*)(Y1 + (row + 1) * 2048 + 1024 + e);
    const float4* pb = (const float4*)(b1 + e);
    float f[8];
    #pragma unroll
    for (int q = 0; q < 2; q++) {
        float4 a = p0[q], c = p1[q], d = pb[q];
        f[q*4+0] = a.x + c.x + d.x; f[q*4+1] = a.y + c.y + d.y;
        f[q*4+2] = a.z + c.z + d.z; f[q*4+3] = a.w + c.w + d.w;
    }
    conv8_store(f, oh + (row + 1) * DHALF + e);
    if (t == SS - 1) {
        float* dst = lf2_out + (size_t)b * DHALF + e;
        #pragma unroll
        for (int j = 0; j < 8; j++) dst[j] = f[j];
    }
}

__global__ __launch_bounds__(128)
void o1e_extras(const float* __restrict__ lf2c, __half* __restrict__ oh)
{
    const int idx = blockIdx.x, e = threadIdx.x * 8;
    size_t row;
    float f[8] = {0, 0, 0, 0, 0, 0, 0, 0};
    if (idx < BB) {
        row = (size_t)idx * STRIDE_T;
        const float4* src = (const float4*)(lf2c + (size_t)idx * DHALF + e);
        float4 v0 = src[0], v1 = src[1];
        f[0]=v0.x; f[1]=v0.y; f[2]=v0.z; f[3]=v0.w; f[4]=v1.x; f[5]=v1.y; f[6]=v1.z; f[7]=v1.w;
    } else {
        row = (size_t)MVAL + (idx - BB);
    }
    conv8_store(f, oh + row * DHALF + e);
}

__global__ __launch_bounds__(256)
void combine2_rms(const float* __restrict__ Y2, const float* __restrict__ b2,
                  const float* __restrict__ x, const float* __restrict__ lnw,
                  float* __restrict__ out)
{
    const int g = blockIdx.x, b = g / SS, t = g % SS;
    const size_t row = (size_t)b * STRIDE_T + t;
    const float4* p0 = (const float4*)(Y2 + row * 4096);
    const float4* p1 = (const float4*)(Y2 + (row + 1) * 4096 + 2048);
    const float4* px = (const float4*)(x + (size_t)g * DD);
    const float4* pb = (const float4*)b2;
    float4 v[2];
    float s = 0.f;
    #pragma unroll
    for (int r = 0; r < 2; r++) {
        const int i = threadIdx.x + r * 256;
        float4 a = p0[i], c = p1[i], d = pb[i], xr = px[i];
        v[r].x = a.x + c.x + d.x + xr.x; v[r].y = a.y + c.y + d.y + xr.y;
        v[r].z = a.z + c.z + d.z + xr.z; v[r].w = a.w + c.w + d.w + xr.w;
        s += v[r].x*v[r].x + v[r].y*v[r].y + v[r].z*v[r].z + v[r].w*v[r].w;
    }
    __shared__ float red[8];
    #pragma unroll
    for (int o = 16; o; o >>= 1) s += __shfl_down_sync(0xffffffffu, s, o);
    if ((threadIdx.x & 31) == 0) red[threadIdx.x >> 5] = s;
    __syncthreads();
    if (threadIdx.x < 32) {
        float tt = (threadIdx.x < 8) ? red[threadIdx.x] : 0.f;
        #pragma unroll
        for (int o = 4; o; o >>= 1) tt += __shfl_down_sync(0xffffffffu, tt, o);
        if (threadIdx.x == 0) red[0] = tt;
    }
    __syncthreads();
    const float inv = rsqrtf(red[0] * (1.0f / DD) + 1e-6f);
    float4* orow = (float4*)(out + (size_t)g * DD);
    const float4* pw = (const float4*)lnw;
    #pragma unroll
    for (int r = 0; r < 2; r++) {
        const int i = threadIdx.x + r * 256;
        float4 w = pw[i];
        orow[i] = make_float4(v[r].x * inv * w.x, v[r].y * inv * w.y,
                              v[r].z * inv * w.z, v[r].w * inv * w.w);
    }
}

__global__ void write_lf1(const float* __restrict__ x, float* __restrict__ out_lf1)
{
    int i = blockIdx.x * blockDim.x + threadIdx.x;
    if (i < BB * DD) {
        int b = i / DD, d = i % DD;
        out_lf1[i] = x[((size_t)b * SS + SS - 1) * DD + d];
    }
}

extern "C" void kernel_launch(void* const* d_in, const int* in_sizes, int n_in,
                              void* d_out, int out_size)
{
    const float* x    = (const float*)d_in[0];
    const float* lf1c = (const float*)d_in[1];
    const float* lf2c = (const float*)d_in[2];
    const float* w1   = (const float*)d_in[3];
    const float* b1   = (const float*)d_in[4];
    const float* w2   = (const float*)d_in[5];
    const float* b2   = (const float*)d_in[6];
    const float* lnw  = (const float*)d_in[7];
    float* out = (float*)d_out;

    __half *xh, *w1c, *w2c, *oh;
    float *Y, *sink;
    cudaGetSymbolAddress((void**)&xh,  g_xe);
    cudaGetSymbolAddress((void**)&w1c, g_w1c);
    cudaGetSymbolAddress((void**)&w2c, g_w2c);
    cudaGetSymbolAddress((void**)&oh,  g_o1);
    cudaGetSymbolAddress((void**)&Y,   g_Y);
    cudaGetSymbolAddress((void**)&sink, g_sink);

    cudaFuncSetAttribute(gemm_mma<2048, 2048>,
                         cudaFuncAttributeMaxDynamicSharedMemorySize, SMEM_DYN);
    cudaFuncSetAttribute(gemm_mma<1024, 4096>,
                         cudaFuncAttributeMaxDynamicSharedMemorySize, SMEM_DYN);

    const long long main_sz = (long long)MTOK * DD;
    const bool carry = (long long)out_size >= main_sz + BB * DD + BB * DHALF;
    float* lf1_out = carry ? out + main_sz : sink;
    float* lf2_out = carry ? out + main_sz + BB * DD : sink;

    pack_x <<<MPAD, 256>>>(x, lf1c, xh);
    pack_w1<<<2048, 256>>>(w1, w1c);
    pack_w2<<<4096, 128>>>(w2, w2c);
    o1e_extras<<<BB + (MPAD - MVAL), 128>>>(lf2c, oh);

    {   // GEMM1: [MPAD,2048] @ [2048,2048]^T -> Y (stride 2048)
        dim3 grid(2048 / 128, MPAD / 128);
        gemm_mma<2048, 2048><<<grid, 256, SMEM_DYN>>>(xh, w1c, Y);
    }
    combine1<<<MTOK, 128>>>(Y, b1, oh, lf2_out);
    {   // GEMM2: [MPAD,1024] @ [4096,1024]^T -> Y (stride 4096)
        dim3 grid(4096 / 128, MPAD / 128);
        gemm_mma<1024, 4096><<<grid, 256, SMEM_DYN>>>(oh, w2c, Y);
    }
    combine2_rms<<<MTOK, 256>>>(Y, b2, x, lnw, out);
    if (carry) write_lf1<<<(BB * DD + 255) / 256, 256>>>(x, lf1_out);
}